// round 1
// baseline (speedup 1.0000x reference)
#include <cuda_runtime.h>
#include <cuda_bf16.h>
#include <math.h>

#define Hdim 1024
#define Ldim 10
#define Vdim 50257
#define ROWS_PER_BLK 8
#define NB5 ((Vdim + ROWS_PER_BLK - 1) / ROWS_PER_BLK)   // 6283

// ---- scratch (no allocations allowed) ----
__device__ __align__(16) float g_xcat[2 * Hdim];   // [embedded, attn_applied]
__device__ __align__(16) float g_x[Hdim];          // relu(comb)
__device__ __align__(16) float g_hnew[Hdim];       // GRU output
__device__ __align__(16) float g_logits[Vdim];
__device__ float g_pmax[NB5];
__device__ float g_psum[NB5];
__device__ float g_stats[2];                       // {gmax, logZ}

__device__ __forceinline__ float warp_sum(float s) {
#pragma unroll
    for (int o = 16; o; o >>= 1) s += __shfl_down_sync(0xffffffffu, s, o);
    return s;
}

// K1: embedding gather + attention scores + softmax + attn_applied -> g_xcat
// one block, 320 threads (warp l handles score l)
__global__ void k1_attn(const int* __restrict__ inp,
                        const float* __restrict__ hidden,
                        const float* __restrict__ enc,
                        const float* __restrict__ emb,
                        const float* __restrict__ attn_W,
                        const float* __restrict__ attn_b,
                        float* __restrict__ out, int out_size) {
    __shared__ float sw[Ldim];
    int tid = threadIdx.x;
    int warp = tid >> 5, lane = tid & 31;
    int tok = inp[0];
    const float* erow = emb + (size_t)tok * Hdim;

    if (warp < Ldim) {
        const float* wrow = attn_W + (size_t)warp * 2 * Hdim;
        float s = 0.f;
        for (int j = lane; j < Hdim; j += 32)
            s += wrow[j] * erow[j] + wrow[Hdim + j] * hidden[j];
        s = warp_sum(s);
        if (lane == 0) sw[warp] = s + attn_b[warp];
    }
    __syncthreads();
    if (tid == 0) {
        float m = sw[0];
#pragma unroll
        for (int l = 1; l < Ldim; l++) m = fmaxf(m, sw[l]);
        float e[Ldim], ssum = 0.f;
#pragma unroll
        for (int l = 0; l < Ldim; l++) { e[l] = expf(sw[l] - m); ssum += e[l]; }
#pragma unroll
        for (int l = 0; l < Ldim; l++) sw[l] = e[l] / ssum;
    }
    __syncthreads();
    // attention weights to output tail (if layout fits)
    if (tid < Ldim && out_size >= Vdim + Hdim + Ldim)
        out[Vdim + Hdim + tid] = sw[tid];
    // xcat = [embedded, attn_weights @ enc]
    for (int j = tid; j < Hdim; j += blockDim.x) {
        float a = 0.f;
#pragma unroll
        for (int l = 0; l < Ldim; l++) a += sw[l] * enc[l * Hdim + j];
        g_xcat[j] = erow[j];
        g_xcat[Hdim + j] = a;
    }
}

// K2: g_x = relu(comb_W @ g_xcat + comb_b).  warp per row. grid 128 x 256.
__global__ void k2_comb(const float* __restrict__ comb_W,
                        const float* __restrict__ comb_b) {
    int warp = (blockIdx.x * blockDim.x + threadIdx.x) >> 5;
    int lane = threadIdx.x & 31;
    if (warp >= Hdim) return;
    const float4* wr = (const float4*)(comb_W + (size_t)warp * 2 * Hdim);
    const float4* xc = (const float4*)g_xcat;
    float s = 0.f;
#pragma unroll
    for (int k = 0; k < 16; k++) {   // 2048/4 = 512 float4, /32 lanes = 16
        float4 w = wr[lane + 32 * k];
        float4 x = xc[lane + 32 * k];
        s += w.x * x.x + w.y * x.y + w.z * x.z + w.w * x.w;
    }
    s = warp_sum(s);
    if (lane == 0) g_x[warp] = fmaxf(s + comb_b[warp], 0.f);
}

// K3: GRU step. warp per hidden unit i: 6 dot products of length H.
__global__ void k3_gru(const float* __restrict__ hidden,
                       const float* __restrict__ wih,
                       const float* __restrict__ whh,
                       const float* __restrict__ bih,
                       const float* __restrict__ bhh,
                       float* __restrict__ out, int out_size) {
    int warp = (blockIdx.x * blockDim.x + threadIdx.x) >> 5;
    int lane = threadIdx.x & 31;
    if (warp >= Hdim) return;
    const float4* x4 = (const float4*)g_x;
    const float4* h4 = (const float4*)hidden;
    const float4* wir = (const float4*)(wih + (size_t)warp * Hdim);
    const float4* wiz = (const float4*)(wih + (size_t)(warp + Hdim) * Hdim);
    const float4* win = (const float4*)(wih + (size_t)(warp + 2 * Hdim) * Hdim);
    const float4* whr = (const float4*)(whh + (size_t)warp * Hdim);
    const float4* whz = (const float4*)(whh + (size_t)(warp + Hdim) * Hdim);
    const float4* whn = (const float4*)(whh + (size_t)(warp + 2 * Hdim) * Hdim);
    float sir = 0, siz = 0, sin_ = 0, shr = 0, shz = 0, shn = 0;
#pragma unroll
    for (int k = 0; k < 8; k++) {    // 1024/4 = 256 float4, /32 = 8
        int idx = lane + 32 * k;
        float4 xv = x4[idx], hv = h4[idx];
        float4 a;
        a = wir[idx]; sir  += a.x * xv.x + a.y * xv.y + a.z * xv.z + a.w * xv.w;
        a = wiz[idx]; siz  += a.x * xv.x + a.y * xv.y + a.z * xv.z + a.w * xv.w;
        a = win[idx]; sin_ += a.x * xv.x + a.y * xv.y + a.z * xv.z + a.w * xv.w;
        a = whr[idx]; shr  += a.x * hv.x + a.y * hv.y + a.z * hv.z + a.w * hv.w;
        a = whz[idx]; shz  += a.x * hv.x + a.y * hv.y + a.z * hv.z + a.w * hv.w;
        a = whn[idx]; shn  += a.x * hv.x + a.y * hv.y + a.z * hv.z + a.w * hv.w;
    }
    sir = warp_sum(sir); siz = warp_sum(siz); sin_ = warp_sum(sin_);
    shr = warp_sum(shr); shz = warp_sum(shz); shn = warp_sum(shn);
    if (lane == 0) {
        float r = 1.f / (1.f + expf(-((sir + bih[warp]) + (shr + bhh[warp]))));
        float z = 1.f / (1.f + expf(-((siz + bih[Hdim + warp]) + (shz + bhh[Hdim + warp]))));
        float n = tanhf((sin_ + bih[2 * Hdim + warp]) + r * (shn + bhh[2 * Hdim + warp]));
        float hn = (1.f - z) * n + z * hidden[warp];
        g_hnew[warp] = hn;
        if (out_size >= Vdim + Hdim) out[Vdim + warp] = hn;
    }
}

// K5: logits = out_W @ h_new + out_b, plus per-block (max, sumexp) partials.
// 8 rows per block (one per warp), h_new cached in shared.
__global__ void k5_logits(const float* __restrict__ outW,
                          const float* __restrict__ outb) {
    __shared__ __align__(16) float sh[Hdim];
    __shared__ float slog[ROWS_PER_BLK];
    int tid = threadIdx.x;
    int warp = tid >> 5, lane = tid & 31;
    for (int j = tid; j < Hdim; j += blockDim.x) sh[j] = g_hnew[j];
    __syncthreads();
    int row = blockIdx.x * ROWS_PER_BLK + warp;
    if (row < Vdim) {
        const float4* wr = (const float4*)(outW + (size_t)row * Hdim);
        const float4* hh = (const float4*)sh;
        float s = 0.f;
#pragma unroll
        for (int k = 0; k < 8; k++) {
            int idx = lane + 32 * k;
            float4 w = wr[idx];
            float4 h = hh[idx];
            s += w.x * h.x + w.y * h.y + w.z * h.z + w.w * h.w;
        }
        s = warp_sum(s);
        if (lane == 0) {
            float lg = s + outb[row];
            g_logits[row] = lg;
            slog[warp] = lg;
        }
    } else if (lane == 0) {
        slog[warp] = -INFINITY;
    }
    __syncthreads();
    if (tid == 0) {
        float m = slog[0];
#pragma unroll
        for (int w = 1; w < ROWS_PER_BLK; w++) m = fmaxf(m, slog[w]);
        float s = 0.f;
#pragma unroll
        for (int w = 0; w < ROWS_PER_BLK; w++) s += expf(slog[w] - m);
        g_pmax[blockIdx.x] = m;
        g_psum[blockIdx.x] = s;
    }
}

// K6: combine per-block partials into global (max, logZ). One block.
__global__ void k6_reduce() {
    __shared__ float sm[1024], ss[1024];
    int tid = threadIdx.x;
    float m = g_pmax[tid];     // NB5 (6283) > 1024, every thread has data
    float s = g_psum[tid];
    for (int b = tid + 1024; b < NB5; b += 1024) {
        float bm = g_pmax[b], bs = g_psum[b];
        if (bm > m) { s = s * expf(m - bm) + bs; m = bm; }
        else        { s += bs * expf(bm - m); }
    }
    sm[tid] = m; ss[tid] = s;
    __syncthreads();
    for (int o = 512; o; o >>= 1) {
        if (tid < o) {
            float m2 = sm[tid + o], s2 = ss[tid + o];
            if (m2 > sm[tid]) { ss[tid] = ss[tid] * expf(sm[tid] - m2) + s2; sm[tid] = m2; }
            else              { ss[tid] += s2 * expf(m2 - sm[tid]); }
        }
        __syncthreads();
    }
    if (tid == 0) { g_stats[0] = sm[0]; g_stats[1] = logf(ss[0]); }
}

// K7: log_probs write.
__global__ void k7_write(float* __restrict__ out) {
    int v = blockIdx.x * blockDim.x + threadIdx.x;
    if (v < Vdim) out[v] = g_logits[v] - g_stats[0] - g_stats[1];
}

extern "C" void kernel_launch(void* const* d_in, const int* in_sizes, int n_in,
                              void* d_out, int out_size) {
    const int*   inp    = (const int*)  d_in[0];
    const float* hidden = (const float*)d_in[1];
    const float* enc    = (const float*)d_in[2];
    const float* emb    = (const float*)d_in[3];
    const float* attn_W = (const float*)d_in[4];
    const float* attn_b = (const float*)d_in[5];
    const float* comb_W = (const float*)d_in[6];
    const float* comb_b = (const float*)d_in[7];
    const float* gruwih = (const float*)d_in[8];
    const float* gruwhh = (const float*)d_in[9];
    const float* grubih = (const float*)d_in[10];
    const float* grubhh = (const float*)d_in[11];
    const float* out_W  = (const float*)d_in[12];
    const float* out_b  = (const float*)d_in[13];
    float* out = (float*)d_out;

    k1_attn<<<1, 320>>>(inp, hidden, enc, emb, attn_W, attn_b, out, out_size);
    k2_comb<<<128, 256>>>(comb_W, comb_b);
    k3_gru<<<128, 256>>>(hidden, gruwih, gruwhh, grubih, grubhh, out, out_size);
    k5_logits<<<NB5, 256>>>(out_W, out_b);
    k6_reduce<<<1, 1024>>>();
    k7_write<<<(Vdim + 255) / 256, 256>>>(out);
}

// round 2
// speedup vs baseline: 1.3175x; 1.3175x over previous
#include <cuda_runtime.h>
#include <cuda_bf16.h>
#include <math.h>

#define Hdim 1024
#define Ldim 10
#define Vdim 50257
#define ROWS_PER_BLK 32                                   // k5: 16 warps x 2 rows
#define NB5 ((Vdim + ROWS_PER_BLK - 1) / ROWS_PER_BLK)    // 1571
#define NB7 ((Vdim + 255) / 256)                          // 197

// ---- scratch (no allocations allowed) ----
__device__ __align__(16) float g_xcat[2 * Hdim];   // [embedded, attn_applied]
__device__ __align__(16) float g_x[Hdim];          // relu(comb)
__device__ __align__(16) float g_hnew[Hdim];       // GRU output
__device__ __align__(16) float g_logits[Vdim];
__device__ float g_pmax[NB5];
__device__ float g_psum[NB5];

__device__ __forceinline__ float warp_sum(float s) {
#pragma unroll
    for (int o = 16; o; o >>= 1) s += __shfl_down_sync(0xffffffffu, s, o);
    return s;
}

// K1: embedding gather + attention scores + softmax + attn_applied -> g_xcat
// one block, 1024 threads (warps 0..9 -> scores, all threads -> xcat)
__global__ void k1_attn(const int* __restrict__ inp,
                        const float* __restrict__ hidden,
                        const float* __restrict__ enc,
                        const float* __restrict__ emb,
                        const float* __restrict__ attn_W,
                        const float* __restrict__ attn_b,
                        float* __restrict__ out, int out_size) {
    __shared__ float sw[Ldim];
    int tid = threadIdx.x;
    int warp = tid >> 5, lane = tid & 31;
    int tok = inp[0];
    const float* erow = emb + (size_t)tok * Hdim;

    if (warp < Ldim) {
        const float* wrow = attn_W + (size_t)warp * 2 * Hdim;
        float s = 0.f;
        for (int j = lane; j < Hdim; j += 32)
            s += wrow[j] * erow[j] + wrow[Hdim + j] * hidden[j];
        s = warp_sum(s);
        if (lane == 0) sw[warp] = s + attn_b[warp];
    }
    __syncthreads();
    if (tid == 0) {
        float m = sw[0];
#pragma unroll
        for (int l = 1; l < Ldim; l++) m = fmaxf(m, sw[l]);
        float e[Ldim], ssum = 0.f;
#pragma unroll
        for (int l = 0; l < Ldim; l++) { e[l] = expf(sw[l] - m); ssum += e[l]; }
#pragma unroll
        for (int l = 0; l < Ldim; l++) sw[l] = e[l] / ssum;
    }
    __syncthreads();
    if (tid < Ldim && out_size >= Vdim + Hdim + Ldim)
        out[Vdim + Hdim + tid] = sw[tid];
    // xcat = [embedded, attn_weights @ enc]  (one element per thread)
    int j = tid;
    if (j < Hdim) {
        float a = 0.f;
#pragma unroll
        for (int l = 0; l < Ldim; l++) a += sw[l] * enc[l * Hdim + j];
        g_xcat[j] = erow[j];
        g_xcat[Hdim + j] = a;
    }
}

// K2: g_x[row] = relu(comb_W[row,:] . g_xcat + b).  Block per row, 512 threads.
__global__ __launch_bounds__(512) void k2_comb(const float* __restrict__ comb_W,
                                               const float* __restrict__ comb_b) {
    __shared__ float red[16];
    int row = blockIdx.x;
    int tid = threadIdx.x, warp = tid >> 5, lane = tid & 31;
    const float4* wr = (const float4*)(comb_W + (size_t)row * 2 * Hdim);
    float4 w = __ldcs(wr + tid);
    float4 x = ((const float4*)g_xcat)[tid];
    float s = w.x * x.x + w.y * x.y + w.z * x.z + w.w * x.w;
    s = warp_sum(s);
    if (lane == 0) red[warp] = s;
    __syncthreads();
    if (warp == 0) {
        float v = (lane < 16) ? red[lane] : 0.f;
        v = warp_sum(v);
        if (lane == 0) g_x[row] = fmaxf(v + comb_b[row], 0.f);
    }
}

// K3: GRU step. Block per hidden unit (1024 blocks, 256 threads): 6 dot products.
__global__ __launch_bounds__(256) void k3_gru(const float* __restrict__ hidden,
                                              const float* __restrict__ wih,
                                              const float* __restrict__ whh,
                                              const float* __restrict__ bih,
                                              const float* __restrict__ bhh,
                                              float* __restrict__ out, int out_size) {
    __shared__ float red[6][8];
    int u = blockIdx.x;
    int tid = threadIdx.x, warp = tid >> 5, lane = tid & 31;
    float4 xv = ((const float4*)g_x)[tid];
    float4 hv = ((const float4*)hidden)[tid];
    const float4* wir = (const float4*)(wih + (size_t)u * Hdim);
    const float4* wiz = (const float4*)(wih + (size_t)(u + Hdim) * Hdim);
    const float4* win = (const float4*)(wih + (size_t)(u + 2 * Hdim) * Hdim);
    const float4* whr = (const float4*)(whh + (size_t)u * Hdim);
    const float4* whz = (const float4*)(whh + (size_t)(u + Hdim) * Hdim);
    const float4* whn = (const float4*)(whh + (size_t)(u + 2 * Hdim) * Hdim);
    float4 a;
    float s0, s1, s2, s3, s4, s5;
    a = __ldcs(wir + tid); s0 = a.x * xv.x + a.y * xv.y + a.z * xv.z + a.w * xv.w;
    a = __ldcs(wiz + tid); s1 = a.x * xv.x + a.y * xv.y + a.z * xv.z + a.w * xv.w;
    a = __ldcs(win + tid); s2 = a.x * xv.x + a.y * xv.y + a.z * xv.z + a.w * xv.w;
    a = __ldcs(whr + tid); s3 = a.x * hv.x + a.y * hv.y + a.z * hv.z + a.w * hv.w;
    a = __ldcs(whz + tid); s4 = a.x * hv.x + a.y * hv.y + a.z * hv.z + a.w * hv.w;
    a = __ldcs(whn + tid); s5 = a.x * hv.x + a.y * hv.y + a.z * hv.z + a.w * hv.w;
    s0 = warp_sum(s0); s1 = warp_sum(s1); s2 = warp_sum(s2);
    s3 = warp_sum(s3); s4 = warp_sum(s4); s5 = warp_sum(s5);
    if (lane == 0) {
        red[0][warp] = s0; red[1][warp] = s1; red[2][warp] = s2;
        red[3][warp] = s3; red[4][warp] = s4; red[5][warp] = s5;
    }
    __syncthreads();
    if (tid == 0) {
        float g[6];
#pragma unroll
        for (int gi = 0; gi < 6; gi++) {
            float acc = 0.f;
#pragma unroll
            for (int w = 0; w < 8; w++) acc += red[gi][w];
            g[gi] = acc;
        }
        float r = 1.f / (1.f + expf(-((g[0] + bih[u]) + (g[3] + bhh[u]))));
        float z = 1.f / (1.f + expf(-((g[1] + bih[Hdim + u]) + (g[4] + bhh[Hdim + u]))));
        float n = tanhf((g[2] + bih[2 * Hdim + u]) + r * (g[5] + bhh[2 * Hdim + u]));
        float hn = (1.f - z) * n + z * hidden[u];
        g_hnew[u] = hn;
        if (out_size >= Vdim + Hdim) out[Vdim + u] = hn;
    }
}

// K5: logits + per-block (max, sumexp). 512 threads, 16 warps x 2 rows = 32 rows/block.
__global__ __launch_bounds__(512) void k5_logits(const float* __restrict__ outW,
                                                 const float* __restrict__ outb) {
    __shared__ __align__(16) float sh[Hdim];
    __shared__ float slog[ROWS_PER_BLK];
    int tid = threadIdx.x, warp = tid >> 5, lane = tid & 31;
    sh[tid] = g_hnew[tid];
    sh[tid + 512] = g_hnew[tid + 512];
    __syncthreads();
    int row0 = blockIdx.x * ROWS_PER_BLK + warp * 2;
    int row1 = row0 + 1;
    const float4* hh = (const float4*)sh;
    float s0 = 0.f, s1 = 0.f;
    bool v0 = row0 < Vdim, v1 = row1 < Vdim;
    const float4* wr0 = (const float4*)(outW + (size_t)(v0 ? row0 : 0) * Hdim);
    const float4* wr1 = (const float4*)(outW + (size_t)(v1 ? row1 : 0) * Hdim);
#pragma unroll
    for (int k = 0; k < 8; k++) {
        int idx = lane + 32 * k;
        float4 h = hh[idx];
        float4 w0 = __ldcs(wr0 + idx);
        float4 w1 = __ldcs(wr1 + idx);
        s0 += w0.x * h.x + w0.y * h.y + w0.z * h.z + w0.w * h.w;
        s1 += w1.x * h.x + w1.y * h.y + w1.z * h.z + w1.w * h.w;
    }
    s0 = warp_sum(s0);
    s1 = warp_sum(s1);
    if (lane == 0) {
        float lg0 = v0 ? (s0 + outb[row0]) : -INFINITY;
        float lg1 = v1 ? (s1 + outb[row1]) : -INFINITY;
        if (v0) g_logits[row0] = lg0;
        if (v1) g_logits[row1] = lg1;
        slog[warp * 2] = lg0;
        slog[warp * 2 + 1] = lg1;
    }
    __syncthreads();
    if (tid == 0) {
        float m = slog[0];
#pragma unroll
        for (int w = 1; w < ROWS_PER_BLK; w++) m = fmaxf(m, slog[w]);
        float s = 0.f;
#pragma unroll
        for (int w = 0; w < ROWS_PER_BLK; w++) s += expf(slog[w] - m);
        g_pmax[blockIdx.x] = m;
        g_psum[blockIdx.x] = s;
    }
}

// K67: fused global logsumexp reduce (redundant per block, L2-resident) + output write.
__global__ __launch_bounds__(256) void k67_write(float* __restrict__ out) {
    __shared__ float sm[256], ss[256];
    int tid = threadIdx.x;
    float m = -INFINITY, s = 0.f;
    for (int b = tid; b < NB5; b += 256) {
        float bm = g_pmax[b], bs = g_psum[b];
        if (bm > m) { s = s * expf(m - bm) + bs; m = bm; }
        else        { s += bs * expf(bm - m); }
    }
    sm[tid] = m; ss[tid] = s;
    __syncthreads();
#pragma unroll
    for (int o = 128; o; o >>= 1) {
        if (tid < o) {
            float m2 = sm[tid + o], s2 = ss[tid + o];
            if (m2 > sm[tid]) { ss[tid] = ss[tid] * expf(sm[tid] - m2) + s2; sm[tid] = m2; }
            else              { ss[tid] += s2 * expf(m2 - sm[tid]); }
        }
        __syncthreads();
    }
    __shared__ float shift;
    if (tid == 0) shift = sm[0] + logf(ss[0]);
    __syncthreads();
    int v = blockIdx.x * 256 + tid;
    if (v < Vdim) out[v] = g_logits[v] - shift;
}

extern "C" void kernel_launch(void* const* d_in, const int* in_sizes, int n_in,
                              void* d_out, int out_size) {
    const int*   inp    = (const int*)  d_in[0];
    const float* hidden = (const float*)d_in[1];
    const float* enc    = (const float*)d_in[2];
    const float* emb    = (const float*)d_in[3];
    const float* attn_W = (const float*)d_in[4];
    const float* attn_b = (const float*)d_in[5];
    const float* comb_W = (const float*)d_in[6];
    const float* comb_b = (const float*)d_in[7];
    const float* gruwih = (const float*)d_in[8];
    const float* gruwhh = (const float*)d_in[9];
    const float* grubih = (const float*)d_in[10];
    const float* grubhh = (const float*)d_in[11];
    const float* out_W  = (const float*)d_in[12];
    const float* out_b  = (const float*)d_in[13];
    float* out = (float*)d_out;

    k1_attn<<<1, 1024>>>(inp, hidden, enc, emb, attn_W, attn_b, out, out_size);
    k2_comb<<<Hdim, 512>>>(comb_W, comb_b);
    k3_gru<<<Hdim, 256>>>(hidden, gruwih, gruwhh, grubih, grubhh, out, out_size);
    k5_logits<<<NB5, 512>>>(out_W, out_b);
    k67_write<<<NB7, 256>>>(out);
}